// round 5
// baseline (speedup 1.0000x reference)
#include <cuda_runtime.h>
#include <cuda_bf16.h>

// NeuMIP v1, round 5: 4-way neuron split.
//  lane = 4*g + h : g = point-group (0..7), h = neuron quarter (0..3)
//  thread accumulates 8 neurons x 8 points in registers (32 ull),
//  weight LDS per input row: 2 LDS.128/thread, 4 distinct 16B chunks per
//  instruction -> 1 wavefront (halves weight L1 traffic vs round 4).

#define RESOL 512
#define RMASK 511
#define HID 32
#define NSLOPE 0.01f
#define THREADS 256
#define PTS_PER_BLOCK 512
#define ACT_STRIDE 512

typedef unsigned long long ull;

__device__ __forceinline__ float leaky(float x) {
    return fmaxf(x, NSLOPE * x);  // slope < 1
}

__device__ __forceinline__ ull fma2(ull a, ull b, ull c) {
    ull d;
    asm("fma.rn.f32x2 %0, %1, %2, %3;" : "=l"(d) : "l"(a), "l"(b), "l"(c));
    return d;
}

__device__ __forceinline__ ull pack2(float lo, float hi) {
    ull d;
    asm("mov.b64 %0, {%1, %2};" : "=l"(d) : "f"(lo), "f"(hi));
    return d;
}

__device__ __forceinline__ void unpack2(ull v, float& lo, float& hi) {
    asm("mov.b64 {%0, %1}, %2;" : "=f"(lo), "=f"(hi) : "l"(v));
}

// 8-channel bilinear with wrap. Texel = 8 contiguous floats = 2x float4.
__device__ __forceinline__ void bilin8(const float4* __restrict__ t,
                                       float u, float v, float* __restrict__ o) {
    float px = u * (float)RESOL - 0.5f;
    float py = v * (float)RESOL - 0.5f;
    float fpx = floorf(px), fpy = floorf(py);
    float fx = px - fpx, fy = py - fpy;
    int ix = (int)fpx, iy = (int)fpy;
    int x0 = ix & RMASK, x1 = (ix + 1) & RMASK;
    int y0 = iy & RMASK, y1 = (iy + 1) & RMASK;
    float w00 = (1.0f - fx) * (1.0f - fy);
    float w01 = fx * (1.0f - fy);
    float w10 = (1.0f - fx) * fy;
    float w11 = fx * fy;
    const float4* p00 = t + (size_t)(y0 * RESOL + x0) * 2;
    const float4* p01 = t + (size_t)(y0 * RESOL + x1) * 2;
    const float4* p10 = t + (size_t)(y1 * RESOL + x0) * 2;
    const float4* p11 = t + (size_t)(y1 * RESOL + x1) * 2;
    float4 a00 = __ldg(p00),     b00 = __ldg(p00 + 1);
    float4 a01 = __ldg(p01),     b01 = __ldg(p01 + 1);
    float4 a10 = __ldg(p10),     b10 = __ldg(p10 + 1);
    float4 a11 = __ldg(p11),     b11 = __ldg(p11 + 1);
    o[0] = w00 * a00.x + w01 * a01.x + w10 * a10.x + w11 * a11.x;
    o[1] = w00 * a00.y + w01 * a01.y + w10 * a10.y + w11 * a11.y;
    o[2] = w00 * a00.z + w01 * a01.z + w10 * a10.z + w11 * a11.z;
    o[3] = w00 * a00.w + w01 * a01.w + w10 * a10.w + w11 * a11.w;
    o[4] = w00 * b00.x + w01 * b01.x + w10 * b10.x + w11 * b11.x;
    o[5] = w00 * b00.y + w01 * b01.y + w10 * b10.y + w11 * b11.y;
    o[6] = w00 * b00.z + w01 * b01.z + w10 * b10.z + w11 * b11.z;
    o[7] = w00 * b00.w + w01 * b01.w + w10 * b10.w + w11 * b11.w;
}

struct __align__(16) SWeights {
    float ow0T[10 * HID];  float ob0[HID];
    float ow1T[HID * HID]; float ob1[HID];
    float ow2T[HID * HID]; float ob2[HID];
    float ow3[HID];        float ob3[4];
    float rw0T[12 * HID];  float rb0[HID];
    float rw1T[HID * HID]; float rb1[HID];
    float rw2T[HID * HID]; float rb2[HID];
    float rw3[3 * HID];    float rb3[4];
};

__device__ __forceinline__ void scopy(float* dst, const float* src, int n,
                                      int tid, int nt) {
    for (int i = tid; i < n; i += nt) dst[i] = src[i];
}

// src: [32][K] row-major -> dst: [K][32]
__device__ __forceinline__ void tcopy(float* dst, const float* src, int K,
                                      int tid, int nt) {
    for (int idx = tid; idx < HID * K; idx += nt) {
        int j = idx / K, i = idx - j * K;
        dst[i * HID + j] = src[idx];
    }
}

// One layer: 8 output neurons (h*8..h*8+7) for 8 points (p8..p8+7).
// K inputs read from act rows [0..K), outputs written in-place to rows
// [h*8, h*8+8). Warp-level hazards handled by __syncwarp around stores.
template <int K>
__device__ __forceinline__ void layer4(const float* __restrict__ wT,
                                       const float* __restrict__ bias,
                                       float* __restrict__ act,
                                       int p8, int h) {
    ull acc[8][4];
    {
        const ull* b2 = reinterpret_cast<const ull*>(bias + h * 8);
        ull b0 = b2[0], b1 = b2[1], bb2 = b2[2], b3 = b2[3];
#pragma unroll
        for (int p = 0; p < 8; p++) {
            acc[p][0] = b0; acc[p][1] = b1; acc[p][2] = bb2; acc[p][3] = b3;
        }
    }
#pragma unroll
    for (int i = 0; i < K; i++) {
        const float4 a0 = *reinterpret_cast<const float4*>(act + i * ACT_STRIDE + p8);
        const float4 a1 = *reinterpret_cast<const float4*>(act + i * ACT_STRIDE + p8 + 4);
        ull d0 = pack2(a0.x, a0.x), d1 = pack2(a0.y, a0.y);
        ull d2 = pack2(a0.z, a0.z), d3 = pack2(a0.w, a0.w);
        ull d4 = pack2(a1.x, a1.x), d5 = pack2(a1.y, a1.y);
        ull d6 = pack2(a1.z, a1.z), d7 = pack2(a1.w, a1.w);
        const ulonglong2* wp =
            reinterpret_cast<const ulonglong2*>(wT + i * HID + h * 8);
        ulonglong2 wa = wp[0];
        ulonglong2 wb = wp[1];
        ull wq0 = wa.x, wq1 = wa.y, wq2 = wb.x, wq3 = wb.y;
        acc[0][0] = fma2(d0, wq0, acc[0][0]);
        acc[0][1] = fma2(d0, wq1, acc[0][1]);
        acc[0][2] = fma2(d0, wq2, acc[0][2]);
        acc[0][3] = fma2(d0, wq3, acc[0][3]);
        acc[1][0] = fma2(d1, wq0, acc[1][0]);
        acc[1][1] = fma2(d1, wq1, acc[1][1]);
        acc[1][2] = fma2(d1, wq2, acc[1][2]);
        acc[1][3] = fma2(d1, wq3, acc[1][3]);
        acc[2][0] = fma2(d2, wq0, acc[2][0]);
        acc[2][1] = fma2(d2, wq1, acc[2][1]);
        acc[2][2] = fma2(d2, wq2, acc[2][2]);
        acc[2][3] = fma2(d2, wq3, acc[2][3]);
        acc[3][0] = fma2(d3, wq0, acc[3][0]);
        acc[3][1] = fma2(d3, wq1, acc[3][1]);
        acc[3][2] = fma2(d3, wq2, acc[3][2]);
        acc[3][3] = fma2(d3, wq3, acc[3][3]);
        acc[4][0] = fma2(d4, wq0, acc[4][0]);
        acc[4][1] = fma2(d4, wq1, acc[4][1]);
        acc[4][2] = fma2(d4, wq2, acc[4][2]);
        acc[4][3] = fma2(d4, wq3, acc[4][3]);
        acc[5][0] = fma2(d5, wq0, acc[5][0]);
        acc[5][1] = fma2(d5, wq1, acc[5][1]);
        acc[5][2] = fma2(d5, wq2, acc[5][2]);
        acc[5][3] = fma2(d5, wq3, acc[5][3]);
        acc[6][0] = fma2(d6, wq0, acc[6][0]);
        acc[6][1] = fma2(d6, wq1, acc[6][1]);
        acc[6][2] = fma2(d6, wq2, acc[6][2]);
        acc[6][3] = fma2(d6, wq3, acc[6][3]);
        acc[7][0] = fma2(d7, wq0, acc[7][0]);
        acc[7][1] = fma2(d7, wq1, acc[7][1]);
        acc[7][2] = fma2(d7, wq2, acc[7][2]);
        acc[7][3] = fma2(d7, wq3, acc[7][3]);
    }
    __syncwarp();  // all lanes done reading act before overwrite
#pragma unroll
    for (int q = 0; q < 4; q++) {
        float lo[8], hi[8];
#pragma unroll
        for (int p = 0; p < 8; p++) unpack2(acc[p][q], lo[p], hi[p]);
        int r0 = h * 8 + 2 * q;
        float4 v;
        v = make_float4(leaky(lo[0]), leaky(lo[1]), leaky(lo[2]), leaky(lo[3]));
        *reinterpret_cast<float4*>(act + r0 * ACT_STRIDE + p8) = v;
        v = make_float4(leaky(lo[4]), leaky(lo[5]), leaky(lo[6]), leaky(lo[7]));
        *reinterpret_cast<float4*>(act + r0 * ACT_STRIDE + p8 + 4) = v;
        v = make_float4(leaky(hi[0]), leaky(hi[1]), leaky(hi[2]), leaky(hi[3]));
        *reinterpret_cast<float4*>(act + (r0 + 1) * ACT_STRIDE + p8) = v;
        v = make_float4(leaky(hi[4]), leaky(hi[5]), leaky(hi[6]), leaky(hi[7]));
        *reinterpret_cast<float4*>(act + (r0 + 1) * ACT_STRIDE + p8 + 4) = v;
    }
    __syncwarp();  // stores visible before next layer reads
}

__device__ __forceinline__ void bfly2(float& x) {
    x += __shfl_xor_sync(0xffffffffu, x, 1);
    x += __shfl_xor_sync(0xffffffffu, x, 2);
}

__global__ void __launch_bounds__(THREADS, 2)
neumip_kernel(const float* __restrict__ cam,
              const float* __restrict__ light,
              const float* __restrict__ uv,
              const float* __restrict__ offset_tex,
              const float* __restrict__ rgb_tex,
              const float* __restrict__ ow0, const float* __restrict__ ob0,
              const float* __restrict__ ow1, const float* __restrict__ ob1,
              const float* __restrict__ ow2, const float* __restrict__ ob2,
              const float* __restrict__ ow3, const float* __restrict__ ob3,
              const float* __restrict__ rw0, const float* __restrict__ rb0,
              const float* __restrict__ rw1, const float* __restrict__ rb1,
              const float* __restrict__ rw2, const float* __restrict__ rb2,
              const float* __restrict__ rw3, const float* __restrict__ rb3,
              float* __restrict__ out, int n) {
    extern __shared__ float dyn[];
    SWeights* sw = reinterpret_cast<SWeights*>(dyn);
    float* act = dyn + sizeof(SWeights) / 4;  // [32][ACT_STRIDE]

    const int tid = threadIdx.x;
    tcopy(sw->ow0T, ow0, 10, tid, THREADS);  scopy(sw->ob0, ob0, HID, tid, THREADS);
    tcopy(sw->ow1T, ow1, HID, tid, THREADS); scopy(sw->ob1, ob1, HID, tid, THREADS);
    tcopy(sw->ow2T, ow2, HID, tid, THREADS); scopy(sw->ob2, ob2, HID, tid, THREADS);
    scopy(sw->ow3, ow3, HID, tid, THREADS);  scopy(sw->ob3, ob3, 1, tid, THREADS);
    tcopy(sw->rw0T, rw0, 12, tid, THREADS);  scopy(sw->rb0, rb0, HID, tid, THREADS);
    tcopy(sw->rw1T, rw1, HID, tid, THREADS); scopy(sw->rb1, rb1, HID, tid, THREADS);
    tcopy(sw->rw2T, rw2, HID, tid, THREADS); scopy(sw->rb2, rb2, HID, tid, THREADS);
    scopy(sw->rw3, rw3, 3 * HID, tid, THREADS); scopy(sw->rb3, rb3, 3, tid, THREADS);
    __syncthreads();

    const int lane = tid & 31;
    const int warp = tid >> 5;
    const int g = lane >> 2;
    const int h = lane & 3;
    const int p8 = warp * 64 + g * 8;            // 8-point group base
    const int block_base = blockIdx.x * PTS_PER_BLOCK;
    if (block_base >= n) return;

    const float2* cam2 = reinterpret_cast<const float2*>(cam);
    const float2* uv2p = reinterpret_cast<const float2*>(uv);
    const float2* li2 = reinterpret_cast<const float2*>(light);

    // ---- gather phase: each thread gathers 2 points (lp = p8 + 2h + j) ----
#pragma unroll
    for (int j = 0; j < 2; j++) {
        int lp = p8 + 2 * h + j;
        int gp = block_base + lp;
        float2 c2 = __ldg(cam2 + gp);
        float2 t2 = __ldg(uv2p + gp);
        float lat[8];
        bilin8(reinterpret_cast<const float4*>(offset_tex), t2.x, t2.y, lat);
#pragma unroll
        for (int c = 0; c < 8; c++) act[c * ACT_STRIDE + lp] = lat[c];
        act[8 * ACT_STRIDE + lp] = c2.x;
        act[9 * ACT_STRIDE + lp] = c2.y;
    }
    __syncwarp();

    // ---- depth MLP ----
    layer4<10>(sw->ow0T, sw->ob0, act, p8, h);
    layer4<HID>(sw->ow1T, sw->ob1, act, p8, h);
    layer4<HID>(sw->ow2T, sw->ob2, act, p8, h);

    // depth head: partial over own 8 rows for 8 pts, butterfly over h lanes
    float4 ds0 = make_float4(0.f, 0.f, 0.f, 0.f);
    float4 ds1 = ds0;
#pragma unroll
    for (int c = 0; c < 8; c++) {
        int row = h * 8 + c;
        float w = sw->ow3[row];
        float4 v0 = *reinterpret_cast<const float4*>(act + row * ACT_STRIDE + p8);
        float4 v1 = *reinterpret_cast<const float4*>(act + row * ACT_STRIDE + p8 + 4);
        ds0.x = fmaf(v0.x, w, ds0.x); ds0.y = fmaf(v0.y, w, ds0.y);
        ds0.z = fmaf(v0.z, w, ds0.z); ds0.w = fmaf(v0.w, w, ds0.w);
        ds1.x = fmaf(v1.x, w, ds1.x); ds1.y = fmaf(v1.y, w, ds1.y);
        ds1.z = fmaf(v1.z, w, ds1.z); ds1.w = fmaf(v1.w, w, ds1.w);
    }
    bfly2(ds0.x); bfly2(ds0.y); bfly2(ds0.z); bfly2(ds0.w);
    bfly2(ds1.x); bfly2(ds1.y); bfly2(ds1.z); bfly2(ds1.w);
    float ob3v = sw->ob3[0];
    // thread's 2 points are local indices 2h, 2h+1 within the 8-pt group
    float dep0, dep1;
    if (h & 2) { dep0 = (h & 1) ? ds1.z : ds1.x; dep1 = (h & 1) ? ds1.w : ds1.y; }
    else       { dep0 = (h & 1) ? ds0.z : ds0.x; dep1 = (h & 1) ? ds0.w : ds0.y; }
    dep0 += ob3v; dep1 += ob3v;
    __syncwarp();

    // ---- parallax + rgb gather: fill rows 0..11 for the 2 points ----
#pragma unroll
    for (int j = 0; j < 2; j++) {
        int lp = p8 + 2 * h + j;
        int gp = block_base + lp;
        float dep = j ? dep1 : dep0;
        float2 c2 = __ldg(cam2 + gp);
        float2 t2 = __ldg(uv2p + gp);
        float2 l2 = __ldg(li2 + gp);
        float z = sqrtf(fmaxf(1.0f - (c2.x * c2.x + c2.y * c2.y), 1e-6f));
        float sc = dep / z;
        float u1 = t2.x + c2.x * sc;
        float v1 = t2.y + c2.y * sc;
        float lat[8];
        bilin8(reinterpret_cast<const float4*>(rgb_tex), u1, v1, lat);
        act[0 * ACT_STRIDE + lp] = l2.x;
        act[1 * ACT_STRIDE + lp] = l2.y;
        act[2 * ACT_STRIDE + lp] = c2.x;
        act[3 * ACT_STRIDE + lp] = c2.y;
#pragma unroll
        for (int c = 0; c < 8; c++) act[(4 + c) * ACT_STRIDE + lp] = lat[c];
    }
    __syncwarp();

    // ---- rgb MLP ----
    layer4<12>(sw->rw0T, sw->rb0, act, p8, h);
    layer4<HID>(sw->rw1T, sw->rb1, act, p8, h);
    layer4<HID>(sw->rw2T, sw->rb2, act, p8, h);

    // rgb head: 3 outputs x 8 pts
    float4 r00 = make_float4(0.f, 0.f, 0.f, 0.f), r01 = r00;
    float4 r10 = r00, r11 = r00, r20 = r00, r21 = r00;
#pragma unroll
    for (int c = 0; c < 8; c++) {
        int row = h * 8 + c;
        float w0 = sw->rw3[0 * HID + row];
        float w1 = sw->rw3[1 * HID + row];
        float w2 = sw->rw3[2 * HID + row];
        float4 v0 = *reinterpret_cast<const float4*>(act + row * ACT_STRIDE + p8);
        float4 v1 = *reinterpret_cast<const float4*>(act + row * ACT_STRIDE + p8 + 4);
        r00.x = fmaf(v0.x, w0, r00.x); r00.y = fmaf(v0.y, w0, r00.y);
        r00.z = fmaf(v0.z, w0, r00.z); r00.w = fmaf(v0.w, w0, r00.w);
        r01.x = fmaf(v1.x, w0, r01.x); r01.y = fmaf(v1.y, w0, r01.y);
        r01.z = fmaf(v1.z, w0, r01.z); r01.w = fmaf(v1.w, w0, r01.w);
        r10.x = fmaf(v0.x, w1, r10.x); r10.y = fmaf(v0.y, w1, r10.y);
        r10.z = fmaf(v0.z, w1, r10.z); r10.w = fmaf(v0.w, w1, r10.w);
        r11.x = fmaf(v1.x, w1, r11.x); r11.y = fmaf(v1.y, w1, r11.y);
        r11.z = fmaf(v1.z, w1, r11.z); r11.w = fmaf(v1.w, w1, r11.w);
        r20.x = fmaf(v0.x, w2, r20.x); r20.y = fmaf(v0.y, w2, r20.y);
        r20.z = fmaf(v0.z, w2, r20.z); r20.w = fmaf(v0.w, w2, r20.w);
        r21.x = fmaf(v1.x, w2, r21.x); r21.y = fmaf(v1.y, w2, r21.y);
        r21.z = fmaf(v1.z, w2, r21.z); r21.w = fmaf(v1.w, w2, r21.w);
    }
    bfly2(r00.x); bfly2(r00.y); bfly2(r00.z); bfly2(r00.w);
    bfly2(r01.x); bfly2(r01.y); bfly2(r01.z); bfly2(r01.w);
    bfly2(r10.x); bfly2(r10.y); bfly2(r10.z); bfly2(r10.w);
    bfly2(r11.x); bfly2(r11.y); bfly2(r11.z); bfly2(r11.w);
    bfly2(r20.x); bfly2(r20.y); bfly2(r20.z); bfly2(r20.w);
    bfly2(r21.x); bfly2(r21.y); bfly2(r21.z); bfly2(r21.w);

    float b0 = sw->rb3[0], b1 = sw->rb3[1], b2 = sw->rb3[2];
    float o00, o01, o02, o10, o11, o12;
    if (h & 2) {
        o00 = (h & 1) ? r01.z : r01.x;  o10 = (h & 1) ? r01.w : r01.y;
        o01 = (h & 1) ? r11.z : r11.x;  o11 = (h & 1) ? r11.w : r11.y;
        o02 = (h & 1) ? r21.z : r21.x;  o12 = (h & 1) ? r21.w : r21.y;
    } else {
        o00 = (h & 1) ? r00.z : r00.x;  o10 = (h & 1) ? r00.w : r00.y;
        o01 = (h & 1) ? r10.z : r10.x;  o11 = (h & 1) ? r10.w : r10.y;
        o02 = (h & 1) ? r20.z : r20.x;  o12 = (h & 1) ? r20.w : r20.y;
    }
    {
        int gp = block_base + p8 + 2 * h;
        out[3 * gp + 0] = o00 + b0;
        out[3 * gp + 1] = o01 + b1;
        out[3 * gp + 2] = o02 + b2;
        out[3 * gp + 3] = o10 + b0;
        out[3 * gp + 4] = o11 + b1;
        out[3 * gp + 5] = o12 + b2;
    }
}

extern "C" void kernel_launch(void* const* d_in, const int* in_sizes, int n_in,
                              void* d_out, int out_size) {
    const float* cam        = (const float*)d_in[0];
    const float* light      = (const float*)d_in[1];
    const float* uv         = (const float*)d_in[2];
    const float* offset_tex = (const float*)d_in[3];
    const float* rgb_tex    = (const float*)d_in[4];
    const float* ow0 = (const float*)d_in[5];
    const float* ob0 = (const float*)d_in[6];
    const float* ow1 = (const float*)d_in[7];
    const float* ob1 = (const float*)d_in[8];
    const float* ow2 = (const float*)d_in[9];
    const float* ob2 = (const float*)d_in[10];
    const float* ow3 = (const float*)d_in[11];
    const float* ob3 = (const float*)d_in[12];
    const float* rw0 = (const float*)d_in[13];
    const float* rb0 = (const float*)d_in[14];
    const float* rw1 = (const float*)d_in[15];
    const float* rb1 = (const float*)d_in[16];
    const float* rw2 = (const float*)d_in[17];
    const float* rb2 = (const float*)d_in[18];
    const float* rw3 = (const float*)d_in[19];
    const float* rb3 = (const float*)d_in[20];

    const int n = in_sizes[0] / 2;  // camera_dir is (B, 2)
    const int smem = (int)sizeof(SWeights) + 32 * ACT_STRIDE * (int)sizeof(float);
    cudaFuncSetAttribute(neumip_kernel,
                         cudaFuncAttributeMaxDynamicSharedMemorySize, smem);
    const int blocks = (n + PTS_PER_BLOCK - 1) / PTS_PER_BLOCK;
    neumip_kernel<<<blocks, THREADS, smem>>>(cam, light, uv, offset_tex, rgb_tex,
                                             ow0, ob0, ow1, ob1, ow2, ob2, ow3, ob3,
                                             rw0, rb0, rw1, rb1, rw2, rb2, rw3, rb3,
                                             (float*)d_out, n);
}

// round 6
// speedup vs baseline: 1.1363x; 1.1363x over previous
#include <cuda_runtime.h>
#include <cuda_bf16.h>

// NeuMIP v1, round 6: all-32-neurons per thread (warp-uniform weight LDS),
// 2 points per thread, activations fully register-resident, FFMA2 math.
//  - weight loads: 4x LDS.128 per input row, warp-uniform -> 1 wf each
//  - no activation smem, no shuffles, no syncwarp in hot path
//  - __launch_bounds__(128, 3): <=170 regs, 12 warps/SM

#define RESOL 512
#define RMASK 511
#define HID 32
#define NSLOPE 0.01f
#define THREADS 128
#define PTS_PER_BLOCK 256

typedef unsigned long long ull;

__device__ __forceinline__ float leaky(float x) {
    return fmaxf(x, NSLOPE * x);  // slope < 1
}

__device__ __forceinline__ ull fma2(ull a, ull b, ull c) {
    ull d;
    asm("fma.rn.f32x2 %0, %1, %2, %3;" : "=l"(d) : "l"(a), "l"(b), "l"(c));
    return d;
}

__device__ __forceinline__ ull pack2(float lo, float hi) {
    ull d;
    asm("mov.b64 %0, {%1, %2};" : "=l"(d) : "f"(lo), "f"(hi));
    return d;
}

__device__ __forceinline__ void unpack2(ull v, float& lo, float& hi) {
    asm("mov.b64 {%0, %1}, %2;" : "=f"(lo), "=f"(hi) : "l"(v));
}

// 8-channel bilinear with wrap. Texel = 8 contiguous floats = 2x float4.
__device__ __forceinline__ void bilin8(const float4* __restrict__ t,
                                       float u, float v, float* __restrict__ o) {
    float px = u * (float)RESOL - 0.5f;
    float py = v * (float)RESOL - 0.5f;
    float fpx = floorf(px), fpy = floorf(py);
    float fx = px - fpx, fy = py - fpy;
    int ix = (int)fpx, iy = (int)fpy;
    int x0 = ix & RMASK, x1 = (ix + 1) & RMASK;
    int y0 = iy & RMASK, y1 = (iy + 1) & RMASK;
    float w00 = (1.0f - fx) * (1.0f - fy);
    float w01 = fx * (1.0f - fy);
    float w10 = (1.0f - fx) * fy;
    float w11 = fx * fy;
    const float4* p00 = t + (size_t)(y0 * RESOL + x0) * 2;
    const float4* p01 = t + (size_t)(y0 * RESOL + x1) * 2;
    const float4* p10 = t + (size_t)(y1 * RESOL + x0) * 2;
    const float4* p11 = t + (size_t)(y1 * RESOL + x1) * 2;
    float4 a00 = __ldg(p00),     b00 = __ldg(p00 + 1);
    float4 a01 = __ldg(p01),     b01 = __ldg(p01 + 1);
    float4 a10 = __ldg(p10),     b10 = __ldg(p10 + 1);
    float4 a11 = __ldg(p11),     b11 = __ldg(p11 + 1);
    o[0] = w00 * a00.x + w01 * a01.x + w10 * a10.x + w11 * a11.x;
    o[1] = w00 * a00.y + w01 * a01.y + w10 * a10.y + w11 * a11.y;
    o[2] = w00 * a00.z + w01 * a01.z + w10 * a10.z + w11 * a11.z;
    o[3] = w00 * a00.w + w01 * a01.w + w10 * a10.w + w11 * a11.w;
    o[4] = w00 * b00.x + w01 * b01.x + w10 * b10.x + w11 * b11.x;
    o[5] = w00 * b00.y + w01 * b01.y + w10 * b10.y + w11 * b11.y;
    o[6] = w00 * b00.z + w01 * b01.z + w10 * b10.z + w11 * b11.z;
    o[7] = w00 * b00.w + w01 * b01.w + w10 * b10.w + w11 * b11.w;
}

struct __align__(16) SWeights {
    float ow0T[10 * HID];  float ob0[HID];
    float ow1T[HID * HID]; float ob1[HID];
    float ow2T[HID * HID]; float ob2[HID];
    float ow3[HID];        float ob3[4];
    float rw0T[12 * HID];  float rb0[HID];
    float rw1T[HID * HID]; float rb1[HID];
    float rw2T[HID * HID]; float rb2[HID];
    float rw3T[3 * HID];   float rb3[4];   // rw3T: [HID][3]? no — packed pairs, see head
};

__device__ __forceinline__ void scopy(float* dst, const float* src, int n,
                                      int tid, int nt) {
    for (int i = tid; i < n; i += nt) dst[i] = src[i];
}

// src: [32][K] row-major -> dst: [K][32]
__device__ __forceinline__ void tcopy(float* dst, const float* src, int K,
                                      int tid, int nt) {
    for (int idx = tid; idx < HID * K; idx += nt) {
        int j = idx / K, i = idx - j * K;
        dst[i * HID + j] = src[idx];
    }
}

// One layer, 2 points, all 32 neurons per thread.
// wT: [K][32] in smem (warp-uniform addresses).
template <int K>
__device__ __forceinline__ void layerU(const float* __restrict__ wT,
                                       const float* __restrict__ bias,
                                       const float* __restrict__ in0,
                                       const float* __restrict__ in1,
                                       float* __restrict__ out0,
                                       float* __restrict__ out1) {
    ull acc0[16], acc1[16];
    {
        const ull* b2 = reinterpret_cast<const ull*>(bias);
#pragma unroll
        for (int k = 0; k < 16; k++) { ull b = b2[k]; acc0[k] = b; acc1[k] = b; }
    }
#pragma unroll
    for (int i = 0; i < K; i++) {
        ull a0 = pack2(in0[i], in0[i]);
        ull a1 = pack2(in1[i], in1[i]);
        const ulonglong2* wq = reinterpret_cast<const ulonglong2*>(wT + i * HID);
#pragma unroll
        for (int q = 0; q < 4; q++) {
            ulonglong2 w = wq[q];
            acc0[2 * q]     = fma2(a0, w.x, acc0[2 * q]);
            acc0[2 * q + 1] = fma2(a0, w.y, acc0[2 * q + 1]);
            acc1[2 * q]     = fma2(a1, w.x, acc1[2 * q]);
            acc1[2 * q + 1] = fma2(a1, w.y, acc1[2 * q + 1]);
        }
        const ulonglong2* wq2 =
            reinterpret_cast<const ulonglong2*>(wT + i * HID + 16);
#pragma unroll
        for (int q = 0; q < 4; q++) {
            ulonglong2 w = wq2[q];
            acc0[8 + 2 * q]     = fma2(a0, w.x, acc0[8 + 2 * q]);
            acc0[8 + 2 * q + 1] = fma2(a0, w.y, acc0[8 + 2 * q + 1]);
            acc1[8 + 2 * q]     = fma2(a1, w.x, acc1[8 + 2 * q]);
            acc1[8 + 2 * q + 1] = fma2(a1, w.y, acc1[8 + 2 * q + 1]);
        }
    }
#pragma unroll
    for (int k = 0; k < 16; k++) {
        float x, y;
        unpack2(acc0[k], x, y);
        out0[2 * k] = leaky(x); out0[2 * k + 1] = leaky(y);
        unpack2(acc1[k], x, y);
        out1[2 * k] = leaky(x); out1[2 * k + 1] = leaky(y);
    }
}

// Packed dot product of 32-float register array with uniform smem weights.
__device__ __forceinline__ float dot32(const float* __restrict__ w,
                                       const float* __restrict__ v) {
    const ull* w2 = reinterpret_cast<const ull*>(w);
    ull acc = 0;  // (0.0f, 0.0f)
#pragma unroll
    for (int k = 0; k < 16; k++) {
        ull a = pack2(v[2 * k], v[2 * k + 1]);
        acc = fma2(a, w2[k], acc);
    }
    float lo, hi;
    unpack2(acc, lo, hi);
    return lo + hi;
}

__global__ void __launch_bounds__(THREADS, 3)
neumip_kernel(const float* __restrict__ cam,
              const float* __restrict__ light,
              const float* __restrict__ uv,
              const float* __restrict__ offset_tex,
              const float* __restrict__ rgb_tex,
              const float* __restrict__ ow0, const float* __restrict__ ob0,
              const float* __restrict__ ow1, const float* __restrict__ ob1,
              const float* __restrict__ ow2, const float* __restrict__ ob2,
              const float* __restrict__ ow3, const float* __restrict__ ob3,
              const float* __restrict__ rw0, const float* __restrict__ rb0,
              const float* __restrict__ rw1, const float* __restrict__ rb1,
              const float* __restrict__ rw2, const float* __restrict__ rb2,
              const float* __restrict__ rw3, const float* __restrict__ rb3,
              float* __restrict__ out, int n) {
    __shared__ SWeights s;
    const int tid = threadIdx.x;
    tcopy(s.ow0T, ow0, 10, tid, THREADS);  scopy(s.ob0, ob0, HID, tid, THREADS);
    tcopy(s.ow1T, ow1, HID, tid, THREADS); scopy(s.ob1, ob1, HID, tid, THREADS);
    tcopy(s.ow2T, ow2, HID, tid, THREADS); scopy(s.ob2, ob2, HID, tid, THREADS);
    scopy(s.ow3, ow3, HID, tid, THREADS);  scopy(s.ob3, ob3, 1, tid, THREADS);
    tcopy(s.rw0T, rw0, 12, tid, THREADS);  scopy(s.rb0, rb0, HID, tid, THREADS);
    tcopy(s.rw1T, rw1, HID, tid, THREADS); scopy(s.rb1, rb1, HID, tid, THREADS);
    tcopy(s.rw2T, rw2, HID, tid, THREADS); scopy(s.rb2, rb2, HID, tid, THREADS);
    scopy(s.rw3T, rw3, 3 * HID, tid, THREADS); scopy(s.rb3, rb3, 3, tid, THREADS);
    __syncthreads();

    // 2 points per thread
    const int base = blockIdx.x * PTS_PER_BLOCK;
    const int p0 = base + tid;
    const int p1 = p0 + THREADS;
    if (p0 >= n) return;

    const float2* cam2 = reinterpret_cast<const float2*>(cam);
    const float2* uv2p = reinterpret_cast<const float2*>(uv);
    const float2* li2 = reinterpret_cast<const float2*>(light);

    const float2 c0 = __ldg(cam2 + p0);
    const float2 c1 = __ldg(cam2 + p1);
    const float2 t0 = __ldg(uv2p + p0);
    const float2 t1 = __ldg(uv2p + p1);

    // ---- offset texture gather + depth MLP ----
    float in0[12], in1[12];
    bilin8(reinterpret_cast<const float4*>(offset_tex), t0.x, t0.y, in0);
    bilin8(reinterpret_cast<const float4*>(offset_tex), t1.x, t1.y, in1);
    in0[8] = c0.x; in0[9] = c0.y;
    in1[8] = c1.x; in1[9] = c1.y;

    float ha0[HID], ha1[HID], hb0[HID], hb1[HID];
    layerU<10>(s.ow0T, s.ob0, in0, in1, ha0, ha1);
    layerU<HID>(s.ow1T, s.ob1, ha0, ha1, hb0, hb1);
    layerU<HID>(s.ow2T, s.ob2, hb0, hb1, ha0, ha1);

    float dep0 = dot32(s.ow3, ha0) + s.ob3[0];
    float dep1 = dot32(s.ow3, ha1) + s.ob3[0];

    // ---- parallax ----
    float z0 = sqrtf(fmaxf(1.0f - (c0.x * c0.x + c0.y * c0.y), 1e-6f));
    float z1 = sqrtf(fmaxf(1.0f - (c1.x * c1.x + c1.y * c1.y), 1e-6f));
    float s0 = dep0 / z0, s1 = dep1 / z1;
    float u10 = t0.x + c0.x * s0, v10 = t0.y + c0.y * s0;
    float u11 = t1.x + c1.x * s1, v11 = t1.y + c1.y * s1;

    // ---- rgb gather + rgb MLP ----
    const float2 l0 = __ldg(li2 + p0);
    const float2 l1 = __ldg(li2 + p1);
    in0[0] = l0.x; in0[1] = l0.y; in0[2] = c0.x; in0[3] = c0.y;
    in1[0] = l1.x; in1[1] = l1.y; in1[2] = c1.x; in1[3] = c1.y;
    bilin8(reinterpret_cast<const float4*>(rgb_tex), u10, v10, in0 + 4);
    bilin8(reinterpret_cast<const float4*>(rgb_tex), u11, v11, in1 + 4);

    layerU<12>(s.rw0T, s.rb0, in0, in1, ha0, ha1);
    layerU<HID>(s.rw1T, s.rb1, ha0, ha1, hb0, hb1);
    layerU<HID>(s.rw2T, s.rb2, hb0, hb1, ha0, ha1);

#pragma unroll
    for (int c = 0; c < 3; c++) {
        const float* w = s.rw3T + c * HID;
        out[3 * p0 + c] = dot32(w, ha0) + s.rb3[c];
        out[3 * p1 + c] = dot32(w, ha1) + s.rb3[c];
    }
}

extern "C" void kernel_launch(void* const* d_in, const int* in_sizes, int n_in,
                              void* d_out, int out_size) {
    const float* cam        = (const float*)d_in[0];
    const float* light      = (const float*)d_in[1];
    const float* uv         = (const float*)d_in[2];
    const float* offset_tex = (const float*)d_in[3];
    const float* rgb_tex    = (const float*)d_in[4];
    const float* ow0 = (const float*)d_in[5];
    const float* ob0 = (const float*)d_in[6];
    const float* ow1 = (const float*)d_in[7];
    const float* ob1 = (const float*)d_in[8];
    const float* ow2 = (const float*)d_in[9];
    const float* ob2 = (const float*)d_in[10];
    const float* ow3 = (const float*)d_in[11];
    const float* ob3 = (const float*)d_in[12];
    const float* rw0 = (const float*)d_in[13];
    const float* rb0 = (const float*)d_in[14];
    const float* rw1 = (const float*)d_in[15];
    const float* rb1 = (const float*)d_in[16];
    const float* rw2 = (const float*)d_in[17];
    const float* rb2 = (const float*)d_in[18];
    const float* rw3 = (const float*)d_in[19];
    const float* rb3 = (const float*)d_in[20];

    const int n = in_sizes[0] / 2;  // camera_dir is (B, 2)
    const int blocks = (n + PTS_PER_BLOCK - 1) / PTS_PER_BLOCK;
    neumip_kernel<<<blocks, THREADS>>>(cam, light, uv, offset_tex, rgb_tex,
                                       ow0, ob0, ow1, ob1, ow2, ob2, ow3, ob3,
                                       rw0, rb0, rw1, rb1, rw2, rb2, rw3, rb3,
                                       (float*)d_out, n);
}

// round 7
// speedup vs baseline: 1.3270x; 1.1679x over previous
#include <cuda_runtime.h>
#include <cuda_bf16.h>

// NeuMIP v1, round 7: weights in __constant__ memory (constant/uniform port,
// OFF the L1 pipe which is saturated by texture gathers).
//   prep kernel (transpose/pack into __device__ staging)
//   -> cudaMemcpyToSymbolAsync (D2D, capturable)
//   -> main kernel: 1 pt/thread, FFMA2, zero smem, zero block syncs.

#define RESOL 512
#define RMASK 511
#define HID 32
#define NSLOPE 0.01f
#define THREADS 256

typedef unsigned long long ull;

// Constant image: transposed weights [K][32] stored as packed neuron pairs.
struct __align__(16) CW {
    ulonglong2 ow0T[10 * 8];   // [10][32] floats
    ulonglong2 ow1T[32 * 8];
    ulonglong2 ow2T[32 * 8];
    ulonglong2 rw0T[12 * 8];
    ulonglong2 rw1T[32 * 8];
    ulonglong2 rw2T[32 * 8];
    ull ob0[16]; ull ob1[16]; ull ob2[16];
    ull rb0[16]; ull rb1[16]; ull rb2[16];
    ull ow3[16];               // [32] floats
    ull rw3[3][16];            // [3][32] floats
    float ob3; float rb3[3];
};

__constant__ CW cw;
__device__ CW g_stage;

__device__ __forceinline__ float leaky(float x) {
    return fmaxf(x, NSLOPE * x);  // slope < 1
}

__device__ __forceinline__ ull fma2(ull a, ull b, ull c) {
    ull d;
    asm("fma.rn.f32x2 %0, %1, %2, %3;" : "=l"(d) : "l"(a), "l"(b), "l"(c));
    return d;
}

__device__ __forceinline__ ull pack2(float lo, float hi) {
    ull d;
    asm("mov.b64 %0, {%1, %2};" : "=l"(d) : "f"(lo), "f"(hi));
    return d;
}

__device__ __forceinline__ void unpack2(ull v, float& lo, float& hi) {
    asm("mov.b64 {%0, %1}, %2;" : "=f"(lo), "=f"(hi) : "l"(v));
}

// ---------------- prep kernel: transpose + pack into g_stage ----------------

__device__ __forceinline__ void d_tpose(float* dst, const float* src, int K,
                                        int tid, int nt) {
    // src: [32][K] row-major -> dst: [K][32]
    for (int idx = tid; idx < HID * K; idx += nt) {
        int j = idx / K, i = idx - j * K;
        dst[i * HID + j] = src[idx];
    }
}

__device__ __forceinline__ void d_copy(float* dst, const float* src, int n,
                                       int tid, int nt) {
    for (int i = tid; i < n; i += nt) dst[i] = src[i];
}

__global__ void prep_kernel(const float* ow0, const float* ob0,
                            const float* ow1, const float* ob1,
                            const float* ow2, const float* ob2,
                            const float* ow3, const float* ob3,
                            const float* rw0, const float* rb0,
                            const float* rw1, const float* rb1,
                            const float* rw2, const float* rb2,
                            const float* rw3, const float* rb3) {
    const int tid = threadIdx.x, nt = blockDim.x;
    d_tpose((float*)g_stage.ow0T, ow0, 10, tid, nt);
    d_tpose((float*)g_stage.ow1T, ow1, 32, tid, nt);
    d_tpose((float*)g_stage.ow2T, ow2, 32, tid, nt);
    d_tpose((float*)g_stage.rw0T, rw0, 12, tid, nt);
    d_tpose((float*)g_stage.rw1T, rw1, 32, tid, nt);
    d_tpose((float*)g_stage.rw2T, rw2, 32, tid, nt);
    d_copy((float*)g_stage.ob0, ob0, 32, tid, nt);
    d_copy((float*)g_stage.ob1, ob1, 32, tid, nt);
    d_copy((float*)g_stage.ob2, ob2, 32, tid, nt);
    d_copy((float*)g_stage.rb0, rb0, 32, tid, nt);
    d_copy((float*)g_stage.rb1, rb1, 32, tid, nt);
    d_copy((float*)g_stage.rb2, rb2, 32, tid, nt);
    d_copy((float*)g_stage.ow3, ow3, 32, tid, nt);
    d_copy((float*)g_stage.rw3, rw3, 96, tid, nt);
    if (tid == 0) {
        g_stage.ob3 = ob3[0];
        g_stage.rb3[0] = rb3[0];
        g_stage.rb3[1] = rb3[1];
        g_stage.rb3[2] = rb3[2];
    }
}

// ---------------- main kernel ----------------

// 8-channel bilinear with wrap. Texel = 8 contiguous floats = 2x float4.
__device__ __forceinline__ void bilin8(const float4* __restrict__ t,
                                       float u, float v, float* __restrict__ o) {
    float px = u * (float)RESOL - 0.5f;
    float py = v * (float)RESOL - 0.5f;
    float fpx = floorf(px), fpy = floorf(py);
    float fx = px - fpx, fy = py - fpy;
    int ix = (int)fpx, iy = (int)fpy;
    int x0 = ix & RMASK, x1 = (ix + 1) & RMASK;
    int y0 = iy & RMASK, y1 = (iy + 1) & RMASK;
    float w00 = (1.0f - fx) * (1.0f - fy);
    float w01 = fx * (1.0f - fy);
    float w10 = (1.0f - fx) * fy;
    float w11 = fx * fy;
    const float4* p00 = t + (size_t)(y0 * RESOL + x0) * 2;
    const float4* p01 = t + (size_t)(y0 * RESOL + x1) * 2;
    const float4* p10 = t + (size_t)(y1 * RESOL + x0) * 2;
    const float4* p11 = t + (size_t)(y1 * RESOL + x1) * 2;
    float4 a00 = __ldg(p00),     b00 = __ldg(p00 + 1);
    float4 a01 = __ldg(p01),     b01 = __ldg(p01 + 1);
    float4 a10 = __ldg(p10),     b10 = __ldg(p10 + 1);
    float4 a11 = __ldg(p11),     b11 = __ldg(p11 + 1);
    o[0] = w00 * a00.x + w01 * a01.x + w10 * a10.x + w11 * a11.x;
    o[1] = w00 * a00.y + w01 * a01.y + w10 * a10.y + w11 * a11.y;
    o[2] = w00 * a00.z + w01 * a01.z + w10 * a10.z + w11 * a11.z;
    o[3] = w00 * a00.w + w01 * a01.w + w10 * a10.w + w11 * a11.w;
    o[4] = w00 * b00.x + w01 * b01.x + w10 * b10.x + w11 * b11.x;
    o[5] = w00 * b00.y + w01 * b01.y + w10 * b10.y + w11 * b11.y;
    o[6] = w00 * b00.z + w01 * b01.z + w10 * b10.z + w11 * b11.z;
    o[7] = w00 * b00.w + w01 * b01.w + w10 * b10.w + w11 * b11.w;
}

// One layer, 1 point, all 32 neurons. Weights from __constant__ (transposed,
// packed pairs): compile-time offsets -> uniform-port LDC, zero L1 traffic.
template <int K>
__device__ __forceinline__ void layerC(const ulonglong2* __restrict__ wT,
                                       const ull* __restrict__ bias,
                                       const float* __restrict__ in,
                                       float* __restrict__ out) {
    ull acc[16];
#pragma unroll
    for (int k = 0; k < 16; k++) acc[k] = bias[k];
#pragma unroll
    for (int i = 0; i < K; i++) {
        ull a = pack2(in[i], in[i]);
#pragma unroll
        for (int q = 0; q < 8; q++) {
            ulonglong2 w = wT[i * 8 + q];
            acc[2 * q]     = fma2(a, w.x, acc[2 * q]);
            acc[2 * q + 1] = fma2(a, w.y, acc[2 * q + 1]);
        }
    }
#pragma unroll
    for (int k = 0; k < 16; k++) {
        float x, y;
        unpack2(acc[k], x, y);
        out[2 * k]     = leaky(x);
        out[2 * k + 1] = leaky(y);
    }
}

__device__ __forceinline__ float dotC(const ull* __restrict__ w,
                                      const float* __restrict__ v) {
    ull acc = pack2(0.0f, 0.0f);
#pragma unroll
    for (int k = 0; k < 16; k++) {
        acc = fma2(pack2(v[2 * k], v[2 * k + 1]), w[k], acc);
    }
    float lo, hi;
    unpack2(acc, lo, hi);
    return lo + hi;
}

__global__ void __launch_bounds__(THREADS, 2)
neumip_kernel(const float* __restrict__ cam,
              const float* __restrict__ light,
              const float* __restrict__ uv,
              const float* __restrict__ offset_tex,
              const float* __restrict__ rgb_tex,
              float* __restrict__ out, int n) {
    const int p = blockIdx.x * blockDim.x + threadIdx.x;
    if (p >= n) return;

    const float2 c2 = __ldg(reinterpret_cast<const float2*>(cam) + p);
    const float2 t2 = __ldg(reinterpret_cast<const float2*>(uv) + p);
    const float cx = c2.x, cy = c2.y;
    const float u0 = t2.x, v0 = t2.y;

    // ---- offset texture gather + depth MLP ----
    float in[12];
    bilin8(reinterpret_cast<const float4*>(offset_tex), u0, v0, in);
    in[8] = cx;
    in[9] = cy;

    float ha[HID], hb[HID];
    layerC<10>(cw.ow0T, cw.ob0, in, ha);
    layerC<HID>(cw.ow1T, cw.ob1, ha, hb);
    layerC<HID>(cw.ow2T, cw.ob2, hb, ha);

    float depth = dotC(cw.ow3, ha) + cw.ob3;

    // ---- parallax offset ----
    float z = sqrtf(fmaxf(1.0f - (cx * cx + cy * cy), 1e-6f));
    float sc = depth / z;
    float u1 = u0 + cx * sc;
    float v1 = v0 + cy * sc;

    // ---- rgb texture gather + rgb MLP ----
    const float2 l2 = __ldg(reinterpret_cast<const float2*>(light) + p);
    in[0] = l2.x;
    in[1] = l2.y;
    in[2] = cx;
    in[3] = cy;
    bilin8(reinterpret_cast<const float4*>(rgb_tex), u1, v1, in + 4);

    layerC<12>(cw.rw0T, cw.rb0, in, ha);
    layerC<HID>(cw.rw1T, cw.rb1, ha, hb);
    layerC<HID>(cw.rw2T, cw.rb2, hb, ha);

    float o0 = dotC(cw.rw3[0], ha) + cw.rb3[0];
    float o1 = dotC(cw.rw3[1], ha) + cw.rb3[1];
    float o2 = dotC(cw.rw3[2], ha) + cw.rb3[2];
    out[3 * p + 0] = o0;
    out[3 * p + 1] = o1;
    out[3 * p + 2] = o2;
}

extern "C" void kernel_launch(void* const* d_in, const int* in_sizes, int n_in,
                              void* d_out, int out_size) {
    const float* cam        = (const float*)d_in[0];
    const float* light      = (const float*)d_in[1];
    const float* uv         = (const float*)d_in[2];
    const float* offset_tex = (const float*)d_in[3];
    const float* rgb_tex    = (const float*)d_in[4];

    // 1) pack/transpose weights into device staging
    prep_kernel<<<1, 256>>>((const float*)d_in[5],  (const float*)d_in[6],
                            (const float*)d_in[7],  (const float*)d_in[8],
                            (const float*)d_in[9],  (const float*)d_in[10],
                            (const float*)d_in[11], (const float*)d_in[12],
                            (const float*)d_in[13], (const float*)d_in[14],
                            (const float*)d_in[15], (const float*)d_in[16],
                            (const float*)d_in[17], (const float*)d_in[18],
                            (const float*)d_in[19], (const float*)d_in[20]);

    // 2) device-to-device copy into the __constant__ image (capturable)
    void* stage_ptr = nullptr;
    cudaGetSymbolAddress(&stage_ptr, g_stage);
    cudaMemcpyToSymbolAsync(cw, stage_ptr, sizeof(CW), 0,
                            cudaMemcpyDeviceToDevice, 0);

    // 3) main kernel
    const int n = in_sizes[0] / 2;  // camera_dir is (B, 2)
    const int blocks = (n + THREADS - 1) / THREADS;
    neumip_kernel<<<blocks, THREADS>>>(cam, light, uv, offset_tex, rgb_tex,
                                       (float*)d_out, n);
}